// round 7
// baseline (speedup 1.0000x reference)
#include <cuda_runtime.h>

// out[b, j] = prod_{k<=j} cos(x[b,k]) * cos(params[k])
// Closed form of the circuit: product state after RX/RY layers; CNOT chain maps
// Z_j -> Z_0...Z_j (Heisenberg); single-qubit <Z> after RY(p)RX(x)|0> = cos(p)cos(x).
//
// Each thread processes FOUR adjacent rows (160 B, 16B-aligned): all global
// traffic is LDG.128 / STG.128, 10 loads + 10 stores per thread, MLP=10.
// 4096 threads total = 128 warps; single balanced wave.

#define N_WIRES 10
#define ROWS_PER_THREAD 4

__global__ __launch_bounds__(64) void _QuantumGate_65481071395894_kernel(
    const float* __restrict__ x,      // (B, 10)
    const float* __restrict__ params, // (10,)
    float* __restrict__ out,          // (B, 10)
    int B)
{
    int t = blockIdx.x * blockDim.x + threadIdx.x;   // quad index
    int b0 = t * ROWS_PER_THREAD;
    if (b0 >= B) return;

    // params: 3 vector loads (L2-broadcast), then per-wire cos (10 MUFU)
    float4 p0 = __ldg(reinterpret_cast<const float4*>(params));      // p[0..3]
    float4 p1 = __ldg(reinterpret_cast<const float4*>(params) + 1);  // p[4..7]
    float2 p2 = __ldg(reinterpret_cast<const float2*>(params) + 4);  // p[8..9]
    const float pv[N_WIRES] = {p0.x, p0.y, p0.z, p0.w,
                               p1.x, p1.y, p1.z, p1.w, p2.x, p2.y};
    float cp[N_WIRES];
#pragma unroll
    for (int k = 0; k < N_WIRES; k++) cp[k] = __cosf(pv[k]);

    // 4 rows = 160 bytes at offset 160*t -> 16B aligned -> 10x LDG.128, all
    // issued back-to-back before any consumer (MLP=10, one DRAM round trip).
    const float4* xr = reinterpret_cast<const float4*>(x + (size_t)b0 * N_WIRES);
    float xv[ROWS_PER_THREAD * N_WIRES];
#pragma unroll
    for (int i = 0; i < 10; i++) {
        float4 v = __ldg(xr + i);
        xv[4 * i + 0] = v.x;
        xv[4 * i + 1] = v.y;
        xv[4 * i + 2] = v.z;
        xv[4 * i + 3] = v.w;
    }

    // 40 independent MUFU cos, scaled by cos(p); then 4 independent serial
    // prefix-product chains (ILP=4 through the FMA pipe).
    float o[ROWS_PER_THREAD * N_WIRES];
    float r0 = 1.0f, r1 = 1.0f, r2 = 1.0f, r3 = 1.0f;
#pragma unroll
    for (int k = 0; k < N_WIRES; k++) {
        float s = cp[k];
        r0 *= __cosf(xv[0 * N_WIRES + k]) * s; o[0 * N_WIRES + k] = r0;
        r1 *= __cosf(xv[1 * N_WIRES + k]) * s; o[1 * N_WIRES + k] = r1;
        r2 *= __cosf(xv[2 * N_WIRES + k]) * s; o[2 * N_WIRES + k] = r2;
        r3 *= __cosf(xv[3 * N_WIRES + k]) * s; o[3 * N_WIRES + k] = r3;
    }

    float4* orow = reinterpret_cast<float4*>(out + (size_t)b0 * N_WIRES);
#pragma unroll
    for (int i = 0; i < 10; i++) {
        orow[i] = make_float4(o[4 * i + 0], o[4 * i + 1],
                              o[4 * i + 2], o[4 * i + 3]);
    }
}

extern "C" void kernel_launch(void* const* d_in, const int* in_sizes, int n_in,
                              void* d_out, int out_size) {
    const float* x      = (const float*)d_in[0];   // (16384, 10) float32
    const float* params = (const float*)d_in[1];   // (10,) float32
    float* out          = (float*)d_out;           // (16384, 10) float32

    int B = in_sizes[0] / N_WIRES;          // 16384
    int quads = B / ROWS_PER_THREAD;        // 4096 threads
    int threads = 64;
    int blocks = (quads + threads - 1) / threads;   // 64 blocks
    _QuantumGate_65481071395894_kernel<<<blocks, threads>>>(x, params, out, B);
}